// round 2
// baseline (speedup 1.0000x reference)
#include <cuda_runtime.h>
#include <math.h>

#define B_  32768
#define D_  768
#define H_  1024
#define L_  256
#define M_  32

// Scratch (allocation-free): two ping-pong activation buffers sized for the
// widest layer (B x 2H) plus the latent buffer.
__device__ float g_bufA[(size_t)B_ * 2 * H_];
__device__ float g_bufB[(size_t)B_ * 2 * H_];
__device__ float g_z[(size_t)B_ * L_];

// ---------------------------------------------------------------------------
// SGEMM: C[M,N] = A[M,K] @ W[N,K]^T + bias  (optional leaky-relu epilogue)
// 128x128 tile, BK=16, 256 threads, 8x8 per thread, double-buffered smem.
// Assumes M%128==0, N%128==0, K%16==0 (true for all layers here).
// ---------------------------------------------------------------------------
#define BM 128
#define BN 128
#define BKK 16
#define PAD 4

template<int ACT>
__global__ __launch_bounds__(256)
void gemm_bias_kernel(const float* __restrict__ A, const float* __restrict__ W,
                      const float* __restrict__ bias, float* __restrict__ C,
                      int N, int K) {
    __shared__ float As[2][BKK][BM + PAD];
    __shared__ float Ws[2][BKK][BN + PAD];

    const int tid     = threadIdx.x;
    const int rowBase = blockIdx.y * BM;
    const int colBase = blockIdx.x * BN;

    const int tRow = (tid >> 4) * 8;   // 0..120
    const int tCol = (tid & 15) * 8;   // 0..120

    const int lr0 = tid >> 2;          // 0..63
    const int lk  = (tid & 3) * 4;     // 0,4,8,12

    const float* Ag = A + (size_t)rowBase * K;
    const float* Wg = W + (size_t)colBase * K;

    float acc[8][8];
    #pragma unroll
    for (int i = 0; i < 8; i++)
        #pragma unroll
        for (int j = 0; j < 8; j++) acc[i][j] = 0.f;

    const int ktiles = K / BKK;

    float4 a0, a1, w0, w1;
    // prologue: load tile 0
    a0 = *(const float4*)(Ag + (size_t)lr0        * K + lk);
    a1 = *(const float4*)(Ag + (size_t)(lr0 + 64) * K + lk);
    w0 = *(const float4*)(Wg + (size_t)lr0        * K + lk);
    w1 = *(const float4*)(Wg + (size_t)(lr0 + 64) * K + lk);

#define STORE_TILE(buf)                                                        \
    do {                                                                       \
        As[buf][lk + 0][lr0] = a0.x;  As[buf][lk + 1][lr0] = a0.y;             \
        As[buf][lk + 2][lr0] = a0.z;  As[buf][lk + 3][lr0] = a0.w;             \
        As[buf][lk + 0][lr0 + 64] = a1.x; As[buf][lk + 1][lr0 + 64] = a1.y;    \
        As[buf][lk + 2][lr0 + 64] = a1.z; As[buf][lk + 3][lr0 + 64] = a1.w;    \
        Ws[buf][lk + 0][lr0] = w0.x;  Ws[buf][lk + 1][lr0] = w0.y;             \
        Ws[buf][lk + 2][lr0] = w0.z;  Ws[buf][lk + 3][lr0] = w0.w;             \
        Ws[buf][lk + 0][lr0 + 64] = w1.x; Ws[buf][lk + 1][lr0 + 64] = w1.y;    \
        Ws[buf][lk + 2][lr0 + 64] = w1.z; Ws[buf][lk + 3][lr0 + 64] = w1.w;    \
    } while (0)

    STORE_TILE(0);
    __syncthreads();

    for (int kt = 0; kt < ktiles; kt++) {
        const int cur = kt & 1;
        if (kt + 1 < ktiles) {
            const int ko = (kt + 1) * BKK + lk;
            a0 = *(const float4*)(Ag + (size_t)lr0        * K + ko);
            a1 = *(const float4*)(Ag + (size_t)(lr0 + 64) * K + ko);
            w0 = *(const float4*)(Wg + (size_t)lr0        * K + ko);
            w1 = *(const float4*)(Wg + (size_t)(lr0 + 64) * K + ko);
        }

        #pragma unroll
        for (int kk = 0; kk < BKK; kk++) {
            float rA[8], rB[8];
            *(float4*)&rA[0] = *(const float4*)&As[cur][kk][tRow];
            *(float4*)&rA[4] = *(const float4*)&As[cur][kk][tRow + 4];
            *(float4*)&rB[0] = *(const float4*)&Ws[cur][kk][tCol];
            *(float4*)&rB[4] = *(const float4*)&Ws[cur][kk][tCol + 4];
            #pragma unroll
            for (int i = 0; i < 8; i++)
                #pragma unroll
                for (int j = 0; j < 8; j++)
                    acc[i][j] = fmaf(rA[i], rB[j], acc[i][j]);
        }

        if (kt + 1 < ktiles) STORE_TILE(cur ^ 1);
        __syncthreads();
    }
#undef STORE_TILE

    float bv[8];
    #pragma unroll
    for (int j = 0; j < 8; j++) bv[j] = bias[colBase + tCol + j];

    #pragma unroll
    for (int i = 0; i < 8; i++) {
        float* crow = C + (size_t)(rowBase + tRow + i) * N + colBase + tCol;
        float4 o0, o1;
        float v;
        v = acc[i][0] + bv[0]; if (ACT) v = v >= 0.f ? v : 0.2f * v; o0.x = v;
        v = acc[i][1] + bv[1]; if (ACT) v = v >= 0.f ? v : 0.2f * v; o0.y = v;
        v = acc[i][2] + bv[2]; if (ACT) v = v >= 0.f ? v : 0.2f * v; o0.z = v;
        v = acc[i][3] + bv[3]; if (ACT) v = v >= 0.f ? v : 0.2f * v; o0.w = v;
        v = acc[i][4] + bv[4]; if (ACT) v = v >= 0.f ? v : 0.2f * v; o1.x = v;
        v = acc[i][5] + bv[5]; if (ACT) v = v >= 0.f ? v : 0.2f * v; o1.y = v;
        v = acc[i][6] + bv[6]; if (ACT) v = v >= 0.f ? v : 0.2f * v; o1.z = v;
        v = acc[i][7] + bv[7]; if (ACT) v = v >= 0.f ? v : 0.2f * v; o1.w = v;
        *(float4*)(crow)     = o0;
        *(float4*)(crow + 4) = o1;
    }
}

// ---------------------------------------------------------------------------
// Row LayerNorm + leaky-relu, in place. One block (256 threads) per row.
// NV4=1 -> H=1024, NV4=2 -> H=2048. Two-pass (mean, then centered var).
// ---------------------------------------------------------------------------
__device__ __forceinline__ float block_reduce_sum(float val, float* red) {
    const int lane = threadIdx.x & 31;
    const int w    = threadIdx.x >> 5;
    #pragma unroll
    for (int o = 16; o; o >>= 1) val += __shfl_xor_sync(0xffffffffu, val, o);
    if (lane == 0) red[w] = val;
    __syncthreads();
    float t = (lane < 8) ? red[lane] : 0.f;
    if (w == 0) {
        #pragma unroll
        for (int o = 4; o; o >>= 1) t += __shfl_xor_sync(0xffffffffu, t, o);
        if (lane == 0) red[0] = t;
    }
    __syncthreads();
    float r = red[0];
    __syncthreads();
    return r;
}

template<int NV4>
__global__ __launch_bounds__(256)
void ln_lrelu_kernel(float* __restrict__ X, const float* __restrict__ g,
                     const float* __restrict__ b) {
    const int H = NV4 * 1024;
    const int tid = threadIdx.x;
    float* row = X + (size_t)blockIdx.x * H;
    __shared__ float red[8];

    float4 v[NV4];
    float s = 0.f;
    #pragma unroll
    for (int q = 0; q < NV4; q++) {
        v[q] = *(const float4*)(row + (tid + 256 * q) * 4);
        s += v[q].x + v[q].y + v[q].z + v[q].w;
    }
    const float mean = block_reduce_sum(s, red) * (1.f / H);

    float ss = 0.f;
    #pragma unroll
    for (int q = 0; q < NV4; q++) {
        float dx;
        dx = v[q].x - mean; ss += dx * dx;
        dx = v[q].y - mean; ss += dx * dx;
        dx = v[q].z - mean; ss += dx * dx;
        dx = v[q].w - mean; ss += dx * dx;
    }
    const float var  = block_reduce_sum(ss, red) * (1.f / H);
    const float rstd = rsqrtf(var + 1e-5f);

    #pragma unroll
    for (int q = 0; q < NV4; q++) {
        const int col = (tid + 256 * q) * 4;
        const float4 g4 = *(const float4*)(g + col);
        const float4 b4 = *(const float4*)(b + col);
        float4 o;
        float y;
        y = (v[q].x - mean) * rstd * g4.x + b4.x; o.x = y >= 0.f ? y : 0.2f * y;
        y = (v[q].y - mean) * rstd * g4.y + b4.y; o.y = y >= 0.f ? y : 0.2f * y;
        y = (v[q].z - mean) * rstd * g4.z + b4.z; o.z = y >= 0.f ? y : 0.2f * y;
        y = (v[q].w - mean) * rstd * g4.w + b4.w; o.w = y >= 0.f ? y : 0.2f * y;
        *(float4*)(row + col) = o;
    }
}

// ---------------------------------------------------------------------------
// Fused reparameterize + context-memory attention.
// z = mu + eps*exp(0.5*lv); attn = softmax(z @ ctx^T); z_enh = z + 0.1*attn@ctx
// Block = 256 threads = 8 warps, one row per warp. ctx (32x256) in smem.
// ---------------------------------------------------------------------------
__global__ __launch_bounds__(256)
void reparam_attn_kernel(const float* __restrict__ mu, const float* __restrict__ lv,
                         const float* __restrict__ eps, const float* __restrict__ ctx,
                         float* __restrict__ z_enh) {
    __shared__ float ctxs[M_][L_ + 1];
    __shared__ float zs[8][L_];
    __shared__ float attns[8][M_];

    const int tid = threadIdx.x;
    for (int i = tid; i < M_ * L_; i += 256)
        ctxs[i >> 8][i & 255] = ctx[i];
    __syncthreads();

    const int w    = tid >> 5;
    const int lane = tid & 31;
    const size_t row = (size_t)blockIdx.x * 8 + w;
    const float* murow = mu  + row * L_;
    const float* lvrow = lv  + row * L_;
    const float* eprow = eps + row * L_;

    #pragma unroll
    for (int i = 0; i < 8; i++) {
        const int j = lane + 32 * i;
        zs[w][j] = murow[j] + eprow[j] * expf(0.5f * lvrow[j]);
    }
    __syncwarp();

    // lane m computes score_m
    float s = 0.f;
    #pragma unroll 8
    for (int j = 0; j < L_; j++)
        s = fmaf(zs[w][j], ctxs[lane][j], s);

    float mx = s;
    #pragma unroll
    for (int o = 16; o; o >>= 1) mx = fmaxf(mx, __shfl_xor_sync(0xffffffffu, mx, o));
    float e = expf(s - mx);
    float tot = e;
    #pragma unroll
    for (int o = 16; o; o >>= 1) tot += __shfl_xor_sync(0xffffffffu, tot, o);
    attns[w][lane] = e / tot;
    __syncwarp();

    float* orow = z_enh + row * L_;
    #pragma unroll
    for (int i = 0; i < 8; i++) {
        const int j = lane + 32 * i;
        float add = 0.f;
        #pragma unroll
        for (int m = 0; m < M_; m++)
            add = fmaf(attns[w][m], ctxs[m][j], add);
        orow[j] = zs[w][j] + 0.1f * add;
    }
}

// ---------------------------------------------------------------------------
extern "C" void kernel_launch(void* const* d_in, const int* in_sizes, int n_in,
                              void* d_out, int out_size) {
    (void)in_sizes; (void)n_in; (void)out_size;
    const float* x      = (const float*)d_in[0];
    const float* eps    = (const float*)d_in[1];
    const float* enc_w1 = (const float*)d_in[2];
    const float* enc_b1 = (const float*)d_in[3];
    const float* ln1_g  = (const float*)d_in[4];
    const float* ln1_b  = (const float*)d_in[5];
    const float* enc_w2 = (const float*)d_in[6];
    const float* enc_b2 = (const float*)d_in[7];
    const float* ln2_g  = (const float*)d_in[8];
    const float* ln2_b  = (const float*)d_in[9];
    const float* mu_w   = (const float*)d_in[10];
    const float* mu_b   = (const float*)d_in[11];
    const float* lv_w   = (const float*)d_in[12];
    const float* lv_b   = (const float*)d_in[13];
    const float* di_w   = (const float*)d_in[14];
    const float* di_b   = (const float*)d_in[15];
    const float* dec_w1 = (const float*)d_in[16];
    const float* dec_b1 = (const float*)d_in[17];
    const float* dln1_g = (const float*)d_in[18];
    const float* dln1_b = (const float*)d_in[19];
    const float* dec_w2 = (const float*)d_in[20];
    const float* dec_b2 = (const float*)d_in[21];
    const float* dln2_g = (const float*)d_in[22];
    const float* dln2_b = (const float*)d_in[23];
    const float* dec_w3 = (const float*)d_in[24];
    const float* dec_b3 = (const float*)d_in[25];
    const float* ctx    = (const float*)d_in[26];

    float* out     = (float*)d_out;
    float* out_rec = out;
    float* out_mu  = out + (size_t)B_ * D_;
    float* out_lv  = out_mu + (size_t)B_ * L_;

    float *bufA, *bufB, *zbuf;
    cudaGetSymbolAddress((void**)&bufA, g_bufA);
    cudaGetSymbolAddress((void**)&bufB, g_bufB);
    cudaGetSymbolAddress((void**)&zbuf, g_z);

    const dim3 blk(256);
    const dim3 gH (H_ / BN,     B_ / BM);
    const dim3 gL (L_ / BN,     B_ / BM);
    const dim3 g2H(2 * H_ / BN, B_ / BM);
    const dim3 gD (D_ / BN,     B_ / BM);

    // encoder
    gemm_bias_kernel<0><<<gH, blk>>>(x, enc_w1, enc_b1, bufA, H_, D_);
    ln_lrelu_kernel<1><<<B_, blk>>>(bufA, ln1_g, ln1_b);
    gemm_bias_kernel<0><<<gH, blk>>>(bufA, enc_w2, enc_b2, bufB, H_, H_);
    ln_lrelu_kernel<1><<<B_, blk>>>(bufB, ln2_g, ln2_b);
    gemm_bias_kernel<0><<<gL, blk>>>(bufB, mu_w, mu_b, out_mu, L_, H_);
    gemm_bias_kernel<0><<<gL, blk>>>(bufB, lv_w, lv_b, out_lv, L_, H_);
    // reparameterize + context attention
    reparam_attn_kernel<<<B_ / 8, blk>>>(out_mu, out_lv, eps, ctx, zbuf);
    // decoder
    gemm_bias_kernel<1><<<gH, blk>>>(zbuf, di_w, di_b, bufA, H_, L_);
    gemm_bias_kernel<0><<<gH, blk>>>(bufA, dec_w1, dec_b1, bufB, H_, H_);
    ln_lrelu_kernel<1><<<B_, blk>>>(bufB, dln1_g, dln1_b);
    gemm_bias_kernel<0><<<g2H, blk>>>(bufB, dec_w2, dec_b2, bufA, 2 * H_, H_);
    ln_lrelu_kernel<2><<<B_, blk>>>(bufA, dln2_g, dln2_b);
    gemm_bias_kernel<0><<<gD, blk>>>(bufA, dec_w3, dec_b3, out_rec, D_, 2 * H_);
}

// round 4
// speedup vs baseline: 3.5755x; 3.5755x over previous
#include <cuda_runtime.h>
#include <cuda_bf16.h>
#include <cstdint>
#include <math.h>

#define B_  32768
#define D_  768
#define H_  1024
#define L_  256
#define M_  32

// ---------------- helpers ----------------
__device__ __forceinline__ uint32_t smem_to_u32(const void* p) {
    uint32_t a;
    asm("{ .reg .u64 t; cvta.to.shared.u64 t, %1; cvt.u32.u64 %0, t; }" : "=r"(a) : "l"(p));
    return a;
}
__device__ __forceinline__ void cp16(uint32_t dst, const void* src) {
    asm volatile("cp.async.cg.shared.global [%0], [%1], 16;\n" :: "r"(dst), "l"(src) : "memory");
}
#define CP_COMMIT()  asm volatile("cp.async.commit_group;\n" ::: "memory")
#define CP_WAIT(n)   asm volatile("cp.async.wait_group %0;\n" :: "n"(n) : "memory")
#define LDMATRIX_X4(r0, r1, r2, r3, addr) \
    asm volatile("ldmatrix.sync.aligned.m8n8.x4.shared.b16 {%0,%1,%2,%3}, [%4];" \
                 : "=r"(r0), "=r"(r1), "=r"(r2), "=r"(r3) : "r"(addr))
#define MMA_BF16(d, a, b0, b1) \
    asm volatile("mma.sync.aligned.m16n8k16.row.col.f32.bf16.bf16.f32 " \
                 "{%0,%1,%2,%3}, {%4,%5,%6,%7}, {%8,%9}, {%0,%1,%2,%3};" \
                 : "+f"((d)[0]), "+f"((d)[1]), "+f"((d)[2]), "+f"((d)[3]) \
                 : "r"((a)[0]), "r"((a)[1]), "r"((a)[2]), "r"((a)[3]), "r"(b0), "r"(b1))

// ---------------- scratch ----------------
#define WTOT 7340032
#define PMAX ((size_t)B_ * 2 * H_)
__device__ __nv_bfloat16 g_wh[WTOT], g_wl[WTOT];
__device__ __nv_bfloat16 g_p1h[PMAX], g_p1l[PMAX], g_p2h[PMAX], g_p2l[PMAX];
__device__ float g_f32[PMAX];

__device__ __forceinline__ void split2(float v, __nv_bfloat16& h, __nv_bfloat16& l) {
    h = __float2bfloat16(v);
    l = __float2bfloat16(v - __bfloat162float(h));
}

// ---------------- fp32 -> (hi,lo) bf16 split ----------------
__global__ __launch_bounds__(256)
void split_kernel(const float* __restrict__ src, __nv_bfloat16* __restrict__ hi,
                  __nv_bfloat16* __restrict__ lo, int n4) {
    int i = blockIdx.x * 256 + threadIdx.x;
    if (i >= n4) return;
    float4 v = ((const float4*)src)[i];
    __nv_bfloat16 h0, l0, h1, l1, h2, l2, h3, l3;
    split2(v.x, h0, l0); split2(v.y, h1, l1); split2(v.z, h2, l2); split2(v.w, h3, l3);
    ((__nv_bfloat162*)hi)[i * 2]     = __halves2bfloat162(h0, h1);
    ((__nv_bfloat162*)hi)[i * 2 + 1] = __halves2bfloat162(h2, h3);
    ((__nv_bfloat162*)lo)[i * 2]     = __halves2bfloat162(l0, l1);
    ((__nv_bfloat162*)lo)[i * 2 + 1] = __halves2bfloat162(l2, l3);
}

// ---------------- split-bf16 GEMM via mma.sync (HMMA) ----------------
// C[B,N] = A[B,K] @ W[N,K]^T + bias; acc += Ah*Wh + Ah*Wl + Al*Wh (fp32 acc).
// CTA 128x128, BK=32, 256 threads, warp tile 64x32 (warps 2m x 4n).
// smem stage: 4 arrays (Ah, Al, Wh, Wl), each 128 rows x 80B (64B data + pad).
// Row pad 80B => ldmatrix granule (5*r+c)%8 conflict-free.
#define STAGE_B   40960         // 4 * 128 * 80
#define ARR_B     10240         // 128 * 80
#define GSMEM     (2 * STAGE_B) // 81920

template<int OUT_MODE>
__global__ void __launch_bounds__(256, 1)
mma_gemm_kernel(const __nv_bfloat16* __restrict__ Ah, const __nv_bfloat16* __restrict__ Al,
                const __nv_bfloat16* __restrict__ Wh, const __nv_bfloat16* __restrict__ Wl,
                const float* __restrict__ bias, float* __restrict__ Cf,
                __nv_bfloat16* __restrict__ Oh, __nv_bfloat16* __restrict__ Ol,
                int N, int K) {
    extern __shared__ char smem[];
    const uint32_t smem_u = smem_to_u32(smem);
    const int tid  = threadIdx.x;
    const int wid  = tid >> 5, lane = tid & 31;
    const int rowBase = blockIdx.y * 128;
    const int colBase = blockIdx.x * 128;
    const int warpM = wid & 1;      // 0..1  -> 64 rows
    const int warpN = wid >> 1;     // 0..3  -> 32 cols

    // cp.async per-thread mapping (8 chunks of 16B per thread per stage)
    const __nv_bfloat16* gArr[4] = {Ah, Al, Wh, Wl};

    float acc[4][4][4];
    #pragma unroll
    for (int t = 0; t < 4; t++)
        #pragma unroll
        for (int f = 0; f < 4; f++)
            #pragma unroll
            for (int e = 0; e < 4; e++) acc[t][f][e] = 0.f;

    // ldmatrix lane offsets (stage-relative bytes)
    uint32_t aoff[4];
    #pragma unroll
    for (int t = 0; t < 4; t++)
        aoff[t] = (uint32_t)((warpM * 64 + t * 16 + (lane & 15)) * 80 + ((lane >> 4) << 4));
    uint32_t boff[2];
    #pragma unroll
    for (int g = 0; g < 2; g++) {
        int n = warpN * 32 + g * 16 + (lane & 7) + ((lane & 16) ? 8 : 0);
        boff[g] = (uint32_t)(2 * ARR_B + n * 80 + ((lane & 8) ? 16 : 0));
    }

    const int ktiles = K >> 5;

    // stage filler
    auto fill = [&](int s, int kt) {
        const uint32_t stb = smem_u + s * STAGE_B;
        const int kOff = kt * 32;
        #pragma unroll
        for (int it = 0; it < 8; it++) {
            int idx = it * 256 + tid;
            int arr = idx >> 9;            // 0..3
            int r   = (idx >> 2) & 127;
            int c   = idx & 3;
            int gr  = (arr < 2 ? rowBase : colBase) + r;
            const __nv_bfloat16* src = gArr[arr] + (size_t)gr * K + kOff + c * 8;
            cp16(stb + arr * ARR_B + r * 80 + c * 16, src);
        }
        CP_COMMIT();
    };

    fill(0, 0);
    for (int kt = 0; kt < ktiles; kt++) {
        const int s = kt & 1;
        if (kt + 1 < ktiles) { fill(s ^ 1, kt + 1); CP_WAIT(1); }
        else                 { CP_WAIT(0); }
        __syncthreads();

        const uint32_t stb = smem_u + s * STAGE_B;
        #pragma unroll
        for (int kc = 0; kc < 2; kc++) {
            const uint32_t kb = kc * 32;
            uint32_t ah[4][4], al[4][4];
            #pragma unroll
            for (int t = 0; t < 4; t++) {
                LDMATRIX_X4(ah[t][0], ah[t][1], ah[t][2], ah[t][3], stb + aoff[t] + kb);
                LDMATRIX_X4(al[t][0], al[t][1], al[t][2], al[t][3], stb + aoff[t] + ARR_B + kb);
            }
            uint32_t bh[4][2], bl[4][2];
            #pragma unroll
            for (int g = 0; g < 2; g++) {
                uint32_t r0, r1, r2, r3;
                LDMATRIX_X4(r0, r1, r2, r3, stb + boff[g] + kb);
                bh[2 * g][0] = r0; bh[2 * g][1] = r1;
                bh[2 * g + 1][0] = r2; bh[2 * g + 1][1] = r3;
                LDMATRIX_X4(r0, r1, r2, r3, stb + boff[g] + ARR_B + kb);
                bl[2 * g][0] = r0; bl[2 * g][1] = r1;
                bl[2 * g + 1][0] = r2; bl[2 * g + 1][1] = r3;
            }
            #pragma unroll
            for (int t = 0; t < 4; t++)
                #pragma unroll
                for (int f = 0; f < 4; f++) {
                    MMA_BF16(acc[t][f], ah[t], bh[f][0], bh[f][1]);
                    MMA_BF16(acc[t][f], ah[t], bl[f][0], bl[f][1]);
                    MMA_BF16(acc[t][f], al[t], bh[f][0], bh[f][1]);
                }
        }
        __syncthreads();
    }

    // epilogue
    const int mBase = rowBase + warpM * 64;
    const int nBase = colBase + warpN * 32;
    #pragma unroll
    for (int t = 0; t < 4; t++) {
        #pragma unroll
        for (int f = 0; f < 4; f++) {
            const int col = nBase + f * 8 + (lane & 3) * 2;
            const int r0  = mBase + t * 16 + (lane >> 2);
            const float bv0 = __ldg(bias + col), bv1 = __ldg(bias + col + 1);
            float v00 = acc[t][f][0] + bv0, v01 = acc[t][f][1] + bv1;
            float v10 = acc[t][f][2] + bv0, v11 = acc[t][f][3] + bv1;
            if (OUT_MODE == 0) {
                *(float2*)(Cf + (size_t)r0 * N + col)       = make_float2(v00, v01);
                *(float2*)(Cf + (size_t)(r0 + 8) * N + col) = make_float2(v10, v11);
            } else {
                v00 = v00 >= 0.f ? v00 : 0.2f * v00;
                v01 = v01 >= 0.f ? v01 : 0.2f * v01;
                v10 = v10 >= 0.f ? v10 : 0.2f * v10;
                v11 = v11 >= 0.f ? v11 : 0.2f * v11;
                __nv_bfloat16 h0, l0, h1, l1;
                split2(v00, h0, l0); split2(v01, h1, l1);
                *(__nv_bfloat162*)(Oh + (size_t)r0 * N + col) = __halves2bfloat162(h0, h1);
                *(__nv_bfloat162*)(Ol + (size_t)r0 * N + col) = __halves2bfloat162(l0, l1);
                split2(v10, h0, l0); split2(v11, h1, l1);
                *(__nv_bfloat162*)(Oh + (size_t)(r0 + 8) * N + col) = __halves2bfloat162(h0, h1);
                *(__nv_bfloat162*)(Ol + (size_t)(r0 + 8) * N + col) = __halves2bfloat162(l0, l1);
            }
        }
    }
}

// ---------------- LayerNorm + lrelu -> split-bf16 ----------------
__device__ __forceinline__ float block_reduce_sum(float val, float* red) {
    const int lane = threadIdx.x & 31;
    const int w    = threadIdx.x >> 5;
    #pragma unroll
    for (int o = 16; o; o >>= 1) val += __shfl_xor_sync(0xffffffffu, val, o);
    if (lane == 0) red[w] = val;
    __syncthreads();
    float t = (lane < 8) ? red[lane] : 0.f;
    if (w == 0) {
        #pragma unroll
        for (int o = 4; o; o >>= 1) t += __shfl_xor_sync(0xffffffffu, t, o);
        if (lane == 0) red[0] = t;
    }
    __syncthreads();
    float r = red[0];
    __syncthreads();
    return r;
}

template<int NV4>
__global__ __launch_bounds__(256)
void ln_split_kernel(const float* __restrict__ X, const float* __restrict__ g,
                     const float* __restrict__ b, __nv_bfloat16* __restrict__ Oh,
                     __nv_bfloat16* __restrict__ Ol) {
    const int H = NV4 * 1024;
    const int tid = threadIdx.x;
    const float* row = X + (size_t)blockIdx.x * H;
    __shared__ float red[8];

    float4 v[NV4];
    float s = 0.f;
    #pragma unroll
    for (int q = 0; q < NV4; q++) {
        v[q] = *(const float4*)(row + (tid + 256 * q) * 4);
        s += v[q].x + v[q].y + v[q].z + v[q].w;
    }
    const float mean = block_reduce_sum(s, red) * (1.f / H);

    float ss = 0.f;
    #pragma unroll
    for (int q = 0; q < NV4; q++) {
        float dx;
        dx = v[q].x - mean; ss += dx * dx;
        dx = v[q].y - mean; ss += dx * dx;
        dx = v[q].z - mean; ss += dx * dx;
        dx = v[q].w - mean; ss += dx * dx;
    }
    const float var  = block_reduce_sum(ss, red) * (1.f / H);
    const float rstd = rsqrtf(var + 1e-5f);

    __nv_bfloat16* oh = Oh + (size_t)blockIdx.x * H;
    __nv_bfloat16* ol = Ol + (size_t)blockIdx.x * H;
    #pragma unroll
    for (int q = 0; q < NV4; q++) {
        const int col = (tid + 256 * q) * 4;
        const float4 g4 = *(const float4*)(g + col);
        const float4 b4 = *(const float4*)(b + col);
        float y0 = (v[q].x - mean) * rstd * g4.x + b4.x; y0 = y0 >= 0.f ? y0 : 0.2f * y0;
        float y1 = (v[q].y - mean) * rstd * g4.y + b4.y; y1 = y1 >= 0.f ? y1 : 0.2f * y1;
        float y2 = (v[q].z - mean) * rstd * g4.z + b4.z; y2 = y2 >= 0.f ? y2 : 0.2f * y2;
        float y3 = (v[q].w - mean) * rstd * g4.w + b4.w; y3 = y3 >= 0.f ? y3 : 0.2f * y3;
        __nv_bfloat16 h0, l0, h1, l1, h2, l2, h3, l3;
        split2(y0, h0, l0); split2(y1, h1, l1); split2(y2, h2, l2); split2(y3, h3, l3);
        *(__nv_bfloat162*)(oh + col)     = __halves2bfloat162(h0, h1);
        *(__nv_bfloat162*)(oh + col + 2) = __halves2bfloat162(h2, h3);
        *(__nv_bfloat162*)(ol + col)     = __halves2bfloat162(l0, l1);
        *(__nv_bfloat162*)(ol + col + 2) = __halves2bfloat162(l2, l3);
    }
}

// ---------------- reparam + context attention -> split-bf16 ----------------
__global__ __launch_bounds__(256)
void reparam_attn_kernel(const float* __restrict__ mu, const float* __restrict__ lv,
                         const float* __restrict__ eps, const float* __restrict__ ctx,
                         __nv_bfloat16* __restrict__ Zh, __nv_bfloat16* __restrict__ Zl) {
    __shared__ float ctxs[M_][L_ + 1];
    __shared__ float zs[8][L_];
    __shared__ float attns[8][M_];

    const int tid = threadIdx.x;
    for (int i = tid; i < M_ * L_; i += 256)
        ctxs[i >> 8][i & 255] = ctx[i];
    __syncthreads();

    const int w    = tid >> 5;
    const int lane = tid & 31;
    const size_t row = (size_t)blockIdx.x * 8 + w;
    const float* murow = mu  + row * L_;
    const float* lvrow = lv  + row * L_;
    const float* eprow = eps + row * L_;

    #pragma unroll
    for (int i = 0; i < 8; i++) {
        const int j = lane + 32 * i;
        zs[w][j] = murow[j] + eprow[j] * expf(0.5f * lvrow[j]);
    }
    __syncwarp();

    float s = 0.f;
    #pragma unroll 8
    for (int j = 0; j < L_; j++)
        s = fmaf(zs[w][j], ctxs[lane][j], s);

    float mx = s;
    #pragma unroll
    for (int o = 16; o; o >>= 1) mx = fmaxf(mx, __shfl_xor_sync(0xffffffffu, mx, o));
    float e = expf(s - mx);
    float tot = e;
    #pragma unroll
    for (int o = 16; o; o >>= 1) tot += __shfl_xor_sync(0xffffffffu, tot, o);
    attns[w][lane] = e / tot;
    __syncwarp();

    __nv_bfloat16* zh = Zh + row * L_;
    __nv_bfloat16* zl = Zl + row * L_;
    #pragma unroll
    for (int i = 0; i < 8; i++) {
        const int j = lane + 32 * i;
        float add = 0.f;
        #pragma unroll
        for (int m = 0; m < M_; m++)
            add = fmaf(attns[w][m], ctxs[m][j], add);
        float v = zs[w][j] + 0.1f * add;
        __nv_bfloat16 h, l;
        split2(v, h, l);
        zh[j] = h; zl[j] = l;
    }
}

// ---------------------------------------------------------------------------
extern "C" void kernel_launch(void* const* d_in, const int* in_sizes, int n_in,
                              void* d_out, int out_size) {
    (void)in_sizes; (void)n_in; (void)out_size;
    const float* x      = (const float*)d_in[0];
    const float* eps    = (const float*)d_in[1];
    const float* enc_w1 = (const float*)d_in[2];
    const float* enc_b1 = (const float*)d_in[3];
    const float* ln1_g  = (const float*)d_in[4];
    const float* ln1_b  = (const float*)d_in[5];
    const float* enc_w2 = (const float*)d_in[6];
    const float* enc_b2 = (const float*)d_in[7];
    const float* ln2_g  = (const float*)d_in[8];
    const float* ln2_b  = (const float*)d_in[9];
    const float* mu_w   = (const float*)d_in[10];
    const float* mu_b   = (const float*)d_in[11];
    const float* lv_w   = (const float*)d_in[12];
    const float* lv_b   = (const float*)d_in[13];
    const float* di_w   = (const float*)d_in[14];
    const float* di_b   = (const float*)d_in[15];
    const float* dec_w1 = (const float*)d_in[16];
    const float* dec_b1 = (const float*)d_in[17];
    const float* dln1_g = (const float*)d_in[18];
    const float* dln1_b = (const float*)d_in[19];
    const float* dec_w2 = (const float*)d_in[20];
    const float* dec_b2 = (const float*)d_in[21];
    const float* dln2_g = (const float*)d_in[22];
    const float* dln2_b = (const float*)d_in[23];
    const float* dec_w3 = (const float*)d_in[24];
    const float* dec_b3 = (const float*)d_in[25];
    const float* ctx    = (const float*)d_in[26];

    float* out     = (float*)d_out;
    float* out_rec = out;
    float* out_mu  = out + (size_t)B_ * D_;
    float* out_lv  = out_mu + (size_t)B_ * L_;

    __nv_bfloat16 *wh, *wl, *p1h, *p1l, *p2h, *p2l;
    float* f32buf;
    cudaGetSymbolAddress((void**)&wh, g_wh);
    cudaGetSymbolAddress((void**)&wl, g_wl);
    cudaGetSymbolAddress((void**)&p1h, g_p1h);
    cudaGetSymbolAddress((void**)&p1l, g_p1l);
    cudaGetSymbolAddress((void**)&p2h, g_p2h);
    cudaGetSymbolAddress((void**)&p2l, g_p2l);
    cudaGetSymbolAddress((void**)&f32buf, g_f32);

    cudaFuncSetAttribute(mma_gemm_kernel<0>, cudaFuncAttributeMaxDynamicSharedMemorySize, GSMEM);
    cudaFuncSetAttribute(mma_gemm_kernel<1>, cudaFuncAttributeMaxDynamicSharedMemorySize, GSMEM);

    const size_t o_e1 = 0,       o_e2 = 786432,  o_mu = 1835008, o_lv = 2097152;
    const size_t o_di = 2359296, o_d1 = 2621440, o_d2 = 3670016, o_d3 = 5767168;

    const dim3 blk(256);
    auto splt = [&](const float* s, __nv_bfloat16* h, __nv_bfloat16* l, size_t n) {
        int n4 = (int)(n / 4);
        split_kernel<<<(n4 + 255) / 256, blk>>>(s, h, l, n4);
    };

    // splits: input + all weights
    splt(x,      p1h,       p1l,       (size_t)B_ * D_);
    splt(enc_w1, wh + o_e1, wl + o_e1, (size_t)H_ * D_);
    splt(enc_w2, wh + o_e2, wl + o_e2, (size_t)H_ * H_);
    splt(mu_w,   wh + o_mu, wl + o_mu, (size_t)L_ * H_);
    splt(lv_w,   wh + o_lv, wl + o_lv, (size_t)L_ * H_);
    splt(di_w,   wh + o_di, wl + o_di, (size_t)H_ * L_);
    splt(dec_w1, wh + o_d1, wl + o_d1, (size_t)H_ * H_);
    splt(dec_w2, wh + o_d2, wl + o_d2, (size_t)2 * H_ * H_);
    splt(dec_w3, wh + o_d3, wl + o_d3, (size_t)D_ * 2 * H_);

    auto gemm = [&](int mode, const __nv_bfloat16* ah, const __nv_bfloat16* al,
                    size_t wo, const float* bias, float* cf,
                    __nv_bfloat16* oh, __nv_bfloat16* ol, int N, int K) {
        dim3 g(N / 128, B_ / 128);
        if (mode == 0)
            mma_gemm_kernel<0><<<g, blk, GSMEM>>>(ah, al, wh + wo, wl + wo, bias, cf, oh, ol, N, K);
        else
            mma_gemm_kernel<1><<<g, blk, GSMEM>>>(ah, al, wh + wo, wl + wo, bias, cf, oh, ol, N, K);
    };

    // encoder
    gemm(0, p1h, p1l, o_e1, enc_b1, f32buf, nullptr, nullptr, H_, D_);
    ln_split_kernel<1><<<B_, blk>>>(f32buf, ln1_g, ln1_b, p2h, p2l);
    gemm(0, p2h, p2l, o_e2, enc_b2, f32buf, nullptr, nullptr, H_, H_);
    ln_split_kernel<1><<<B_, blk>>>(f32buf, ln2_g, ln2_b, p1h, p1l);
    gemm(0, p1h, p1l, o_mu, mu_b, out_mu, nullptr, nullptr, L_, H_);
    gemm(0, p1h, p1l, o_lv, lv_b, out_lv, nullptr, nullptr, L_, H_);
    // reparameterize + context attention
    reparam_attn_kernel<<<B_ / 8, blk>>>(out_mu, out_lv, eps, ctx, p2h, p2l);
    // decoder
    gemm(1, p2h, p2l, o_di, di_b, nullptr, p1h, p1l, H_, L_);
    gemm(0, p1h, p1l, o_d1, dec_b1, f32buf, nullptr, nullptr, H_, H_);
    ln_split_kernel<1><<<B_, blk>>>(f32buf, dln1_g, dln1_b, p2h, p2l);
    gemm(0, p2h, p2l, o_d2, dec_b2, f32buf, nullptr, nullptr, 2 * H_, H_);
    ln_split_kernel<2><<<B_, blk>>>(f32buf, dln2_g, dln2_b, p1h, p1l);
    gemm(0, p1h, p1l, o_d3, dec_b3, out_rec, nullptr, nullptr, D_, 2 * H_);
}

// round 5
// speedup vs baseline: 3.8484x; 1.0763x over previous
#include <cuda_runtime.h>
#include <cuda_bf16.h>
#include <cstdint>
#include <math.h>

#define B_  32768
#define D_  768
#define H_  1024
#define L_  256
#define M_  32

// ---------------- helpers ----------------
__device__ __forceinline__ uint32_t smem_to_u32(const void* p) {
    uint32_t a;
    asm("{ .reg .u64 t; cvta.to.shared.u64 t, %1; cvt.u32.u64 %0, t; }" : "=r"(a) : "l"(p));
    return a;
}
__device__ __forceinline__ void cp16(uint32_t dst, const void* src) {
    asm volatile("cp.async.cg.shared.global [%0], [%1], 16;\n" :: "r"(dst), "l"(src) : "memory");
}
#define CP_COMMIT()  asm volatile("cp.async.commit_group;\n" ::: "memory")
#define CP_WAIT(n)   asm volatile("cp.async.wait_group %0;\n" :: "n"(n) : "memory")
#define LDMATRIX_X4(r0, r1, r2, r3, addr) \
    asm volatile("ldmatrix.sync.aligned.m8n8.x4.shared.b16 {%0,%1,%2,%3}, [%4];" \
                 : "=r"(r0), "=r"(r1), "=r"(r2), "=r"(r3) : "r"(addr))
#define MMA_BF16(d, a, b0, b1) \
    asm volatile("mma.sync.aligned.m16n8k16.row.col.f32.bf16.bf16.f32 " \
                 "{%0,%1,%2,%3}, {%4,%5,%6,%7}, {%8,%9}, {%0,%1,%2,%3};" \
                 : "+f"((d)[0]), "+f"((d)[1]), "+f"((d)[2]), "+f"((d)[3]) \
                 : "r"((a)[0]), "r"((a)[1]), "r"((a)[2]), "r"((a)[3]), "r"(b0), "r"(b1))

// ---------------- scratch ----------------
#define WTOT 7340032
#define PMAX ((size_t)B_ * 2 * H_)
__device__ __nv_bfloat16 g_wh[WTOT], g_wl[WTOT];
__device__ __nv_bfloat16 g_p1h[PMAX], g_p1l[PMAX], g_p2h[PMAX], g_p2l[PMAX];
__device__ float g_f32[PMAX];
__device__ float g_bias512[512];

__device__ __forceinline__ void split2(float v, __nv_bfloat16& h, __nv_bfloat16& l) {
    h = __float2bfloat16(v);
    l = __float2bfloat16(v - __bfloat162float(h));
}

// ---------------- fp32 -> (hi,lo) bf16 split ----------------
__global__ __launch_bounds__(256)
void split_kernel(const float* __restrict__ src, __nv_bfloat16* __restrict__ hi,
                  __nv_bfloat16* __restrict__ lo, int n4) {
    int i = blockIdx.x * 256 + threadIdx.x;
    if (i >= n4) return;
    float4 v = ((const float4*)src)[i];
    __nv_bfloat16 h0, l0, h1, l1, h2, l2, h3, l3;
    split2(v.x, h0, l0); split2(v.y, h1, l1); split2(v.z, h2, l2); split2(v.w, h3, l3);
    ((__nv_bfloat162*)hi)[i * 2]     = __halves2bfloat162(h0, h1);
    ((__nv_bfloat162*)hi)[i * 2 + 1] = __halves2bfloat162(h2, h3);
    ((__nv_bfloat162*)lo)[i * 2]     = __halves2bfloat162(l0, l1);
    ((__nv_bfloat162*)lo)[i * 2 + 1] = __halves2bfloat162(l2, l3);
}

// ---------------- split-bf16 GEMM via mma.sync (HMMA) ----------------
// C[B,N] = A[B,K] @ W[N,K]^T + bias; acc += Ah*Wh + Ah*Wl + Al*Wh (fp32 acc).
// CTA 128x256, BK=32, 256 threads, warp tile 64x64 (warps 2m x 4n).
// smem stage: [Ah 128x80][Al 128x80][Wh 256x80][Wl 256x80] = 61440 B, 2 stages.
#define ARR_A   10240           // 128 * 80
#define ARR_W   20480           // 256 * 80
#define AW_OFF  (2 * ARR_A)     // 20480
#define STAGE_B (2 * ARR_A + 2 * ARR_W)   // 61440
#define GSMEM   (2 * STAGE_B)             // 122880

template<int OUT_MODE>
__global__ void __launch_bounds__(256, 1)
mma_gemm_kernel(const __nv_bfloat16* __restrict__ Ah, const __nv_bfloat16* __restrict__ Al,
                const __nv_bfloat16* __restrict__ Wh, const __nv_bfloat16* __restrict__ Wl,
                const float* __restrict__ bias, float* __restrict__ Cf,
                __nv_bfloat16* __restrict__ Oh, __nv_bfloat16* __restrict__ Ol,
                int N, int K) {
    extern __shared__ char smem[];
    const uint32_t smem_u = smem_to_u32(smem);
    const int tid  = threadIdx.x;
    const int wid  = tid >> 5, lane = tid & 31;
    const int rowBase = blockIdx.y * 128;
    const int colBase = blockIdx.x * 256;
    const int warpM = wid & 1;      // 0..1  -> 64 rows
    const int warpN = wid >> 1;     // 0..3  -> 64 cols

    float acc[4][8][4];
    #pragma unroll
    for (int t = 0; t < 4; t++)
        #pragma unroll
        for (int f = 0; f < 8; f++)
            #pragma unroll
            for (int e = 0; e < 4; e++) acc[t][f][e] = 0.f;

    // ldmatrix lane offsets (stage-relative bytes)
    uint32_t aoff[4];
    #pragma unroll
    for (int t = 0; t < 4; t++)
        aoff[t] = (uint32_t)((warpM * 64 + t * 16 + (lane & 15)) * 80 + ((lane >> 4) << 4));
    uint32_t boff[4];
    #pragma unroll
    for (int g = 0; g < 4; g++) {
        int n = warpN * 64 + g * 16 + (lane & 7) + ((lane & 16) ? 8 : 0);
        boff[g] = (uint32_t)(AW_OFF + n * 80 + ((lane & 8) ? 16 : 0));
    }

    const int ktiles = K >> 5;

    // stage filler: 3072 16B chunks (A:1024, W:2048), 12 per thread
    auto fill = [&](int s, int kt) {
        const uint32_t stb = smem_u + s * STAGE_B;
        const int kOff = kt * 32;
        #pragma unroll
        for (int it = 0; it < 4; it++) {          // A chunks
            int idx = it * 256 + tid;             // 0..1023
            int arr = idx >> 9;                   // 0:Ah 1:Al
            int r   = (idx >> 2) & 127;
            int c   = idx & 3;
            const __nv_bfloat16* src =
                (arr ? Al : Ah) + (size_t)(rowBase + r) * K + kOff + c * 8;
            cp16(stb + arr * ARR_A + r * 80 + c * 16, src);
        }
        #pragma unroll
        for (int it = 0; it < 8; it++) {          // W chunks
            int idx = it * 256 + tid;             // 0..2047
            int arr = idx >> 10;                  // 0:Wh 1:Wl
            int r   = (idx >> 2) & 255;
            int c   = idx & 3;
            const __nv_bfloat16* src =
                (arr ? Wl : Wh) + (size_t)(colBase + r) * K + kOff + c * 8;
            cp16(stb + AW_OFF + arr * ARR_W + r * 80 + c * 16, src);
        }
        CP_COMMIT();
    };

    fill(0, 0);
    for (int kt = 0; kt < ktiles; kt++) {
        const int s = kt & 1;
        if (kt + 1 < ktiles) { fill(s ^ 1, kt + 1); CP_WAIT(1); }
        else                 { CP_WAIT(0); }
        __syncthreads();

        const uint32_t stb = smem_u + s * STAGE_B;
        #pragma unroll
        for (int kc = 0; kc < 2; kc++) {
            const uint32_t kb = kc * 32;
            uint32_t ah[4][4], al[4][4];
            #pragma unroll
            for (int t = 0; t < 4; t++) {
                LDMATRIX_X4(ah[t][0], ah[t][1], ah[t][2], ah[t][3], stb + aoff[t] + kb);
                LDMATRIX_X4(al[t][0], al[t][1], al[t][2], al[t][3], stb + aoff[t] + ARR_A + kb);
            }
            #pragma unroll
            for (int g = 0; g < 4; g++) {
                uint32_t bh0, bh1, bh2, bh3, bl0, bl1, bl2, bl3;
                LDMATRIX_X4(bh0, bh1, bh2, bh3, stb + boff[g] + kb);
                LDMATRIX_X4(bl0, bl1, bl2, bl3, stb + boff[g] + ARR_W + kb);
                const int f0 = 2 * g, f1 = 2 * g + 1;
                #pragma unroll
                for (int t = 0; t < 4; t++) {
                    MMA_BF16(acc[t][f0], ah[t], bh0, bh1);
                    MMA_BF16(acc[t][f0], ah[t], bl0, bl1);
                    MMA_BF16(acc[t][f0], al[t], bh0, bh1);
                    MMA_BF16(acc[t][f1], ah[t], bh2, bh3);
                    MMA_BF16(acc[t][f1], ah[t], bl2, bl3);
                    MMA_BF16(acc[t][f1], al[t], bh2, bh3);
                }
            }
        }
        __syncthreads();
    }

    // epilogue
    const int mBase = rowBase + warpM * 64;
    const int nBase = colBase + warpN * 64;
    #pragma unroll
    for (int t = 0; t < 4; t++) {
        #pragma unroll
        for (int f = 0; f < 8; f++) {
            const int col = nBase + f * 8 + (lane & 3) * 2;
            const int r0  = mBase + t * 16 + (lane >> 2);
            const float bv0 = __ldg(bias + col), bv1 = __ldg(bias + col + 1);
            float v00 = acc[t][f][0] + bv0, v01 = acc[t][f][1] + bv1;
            float v10 = acc[t][f][2] + bv0, v11 = acc[t][f][3] + bv1;
            if (OUT_MODE == 0) {
                *(float2*)(Cf + (size_t)r0 * N + col)       = make_float2(v00, v01);
                *(float2*)(Cf + (size_t)(r0 + 8) * N + col) = make_float2(v10, v11);
            } else {
                v00 = v00 >= 0.f ? v00 : 0.2f * v00;
                v01 = v01 >= 0.f ? v01 : 0.2f * v01;
                v10 = v10 >= 0.f ? v10 : 0.2f * v10;
                v11 = v11 >= 0.f ? v11 : 0.2f * v11;
                __nv_bfloat16 h0, l0, h1, l1;
                split2(v00, h0, l0); split2(v01, h1, l1);
                *(__nv_bfloat162*)(Oh + (size_t)r0 * N + col) = __halves2bfloat162(h0, h1);
                *(__nv_bfloat162*)(Ol + (size_t)r0 * N + col) = __halves2bfloat162(l0, l1);
                split2(v10, h0, l0); split2(v11, h1, l1);
                *(__nv_bfloat162*)(Oh + (size_t)(r0 + 8) * N + col) = __halves2bfloat162(h0, h1);
                *(__nv_bfloat162*)(Ol + (size_t)(r0 + 8) * N + col) = __halves2bfloat162(l0, l1);
            }
        }
    }
}

// ---------------- LayerNorm + lrelu -> split-bf16 ----------------
__device__ __forceinline__ float block_reduce_sum(float val, float* red) {
    const int lane = threadIdx.x & 31;
    const int w    = threadIdx.x >> 5;
    #pragma unroll
    for (int o = 16; o; o >>= 1) val += __shfl_xor_sync(0xffffffffu, val, o);
    if (lane == 0) red[w] = val;
    __syncthreads();
    float t = (lane < 8) ? red[lane] : 0.f;
    if (w == 0) {
        #pragma unroll
        for (int o = 4; o; o >>= 1) t += __shfl_xor_sync(0xffffffffu, t, o);
        if (lane == 0) red[0] = t;
    }
    __syncthreads();
    float r = red[0];
    __syncthreads();
    return r;
}

template<int NV4>
__global__ __launch_bounds__(256)
void ln_split_kernel(const float* __restrict__ X, const float* __restrict__ g,
                     const float* __restrict__ b, __nv_bfloat16* __restrict__ Oh,
                     __nv_bfloat16* __restrict__ Ol) {
    const int H = NV4 * 1024;
    const int tid = threadIdx.x;
    const float* row = X + (size_t)blockIdx.x * H;
    __shared__ float red[8];

    float4 v[NV4];
    float s = 0.f;
    #pragma unroll
    for (int q = 0; q < NV4; q++) {
        v[q] = *(const float4*)(row + (tid + 256 * q) * 4);
        s += v[q].x + v[q].y + v[q].z + v[q].w;
    }
    const float mean = block_reduce_sum(s, red) * (1.f / H);

    float ss = 0.f;
    #pragma unroll
    for (int q = 0; q < NV4; q++) {
        float dx;
        dx = v[q].x - mean; ss += dx * dx;
        dx = v[q].y - mean; ss += dx * dx;
        dx = v[q].z - mean; ss += dx * dx;
        dx = v[q].w - mean; ss += dx * dx;
    }
    const float var  = block_reduce_sum(ss, red) * (1.f / H);
    const float rstd = rsqrtf(var + 1e-5f);

    __nv_bfloat16* oh = Oh + (size_t)blockIdx.x * H;
    __nv_bfloat16* ol = Ol + (size_t)blockIdx.x * H;
    #pragma unroll
    for (int q = 0; q < NV4; q++) {
        const int col = (tid + 256 * q) * 4;
        const float4 g4 = *(const float4*)(g + col);
        const float4 b4 = *(const float4*)(b + col);
        float y0 = (v[q].x - mean) * rstd * g4.x + b4.x; y0 = y0 >= 0.f ? y0 : 0.2f * y0;
        float y1 = (v[q].y - mean) * rstd * g4.y + b4.y; y1 = y1 >= 0.f ? y1 : 0.2f * y1;
        float y2 = (v[q].z - mean) * rstd * g4.z + b4.z; y2 = y2 >= 0.f ? y2 : 0.2f * y2;
        float y3 = (v[q].w - mean) * rstd * g4.w + b4.w; y3 = y3 >= 0.f ? y3 : 0.2f * y3;
        __nv_bfloat16 h0, l0, h1, l1, h2, l2, h3, l3;
        split2(y0, h0, l0); split2(y1, h1, l1); split2(y2, h2, l2); split2(y3, h3, l3);
        *(__nv_bfloat162*)(oh + col)     = __halves2bfloat162(h0, h1);
        *(__nv_bfloat162*)(oh + col + 2) = __halves2bfloat162(h2, h3);
        *(__nv_bfloat162*)(ol + col)     = __halves2bfloat162(l0, l1);
        *(__nv_bfloat162*)(ol + col + 2) = __halves2bfloat162(l2, l3);
    }
}

// ---------------- reparam + context attention -> split-bf16 ----------------
// muv: [B, 512], cols 0-255 = mu, cols 256-511 = logvar. Also copies mu/lv
// to the output buffers.
__global__ __launch_bounds__(256)
void reparam_attn_kernel(const float* __restrict__ muv, const float* __restrict__ eps,
                         const float* __restrict__ ctx,
                         float* __restrict__ out_mu, float* __restrict__ out_lv,
                         __nv_bfloat16* __restrict__ Zh, __nv_bfloat16* __restrict__ Zl) {
    __shared__ float ctxs[M_][L_ + 1];
    __shared__ float zs[8][L_];
    __shared__ float attns[8][M_];

    const int tid = threadIdx.x;
    for (int i = tid; i < M_ * L_; i += 256)
        ctxs[i >> 8][i & 255] = ctx[i];
    __syncthreads();

    const int w    = tid >> 5;
    const int lane = tid & 31;
    const size_t row = (size_t)blockIdx.x * 8 + w;
    const float* mvrow = muv + row * 512;
    const float* eprow = eps + row * L_;

    #pragma unroll
    for (int i = 0; i < 8; i++) {
        const int j = lane + 32 * i;
        const float mu = mvrow[j], lv = mvrow[256 + j];
        out_mu[row * L_ + j] = mu;
        out_lv[row * L_ + j] = lv;
        zs[w][j] = mu + eprow[j] * expf(0.5f * lv);
    }
    __syncwarp();

    float s = 0.f;
    #pragma unroll 8
    for (int j = 0; j < L_; j++)
        s = fmaf(zs[w][j], ctxs[lane][j], s);

    float mx = s;
    #pragma unroll
    for (int o = 16; o; o >>= 1) mx = fmaxf(mx, __shfl_xor_sync(0xffffffffu, mx, o));
    float e = expf(s - mx);
    float tot = e;
    #pragma unroll
    for (int o = 16; o; o >>= 1) tot += __shfl_xor_sync(0xffffffffu, tot, o);
    attns[w][lane] = e / tot;
    __syncwarp();

    __nv_bfloat16* zh = Zh + row * L_;
    __nv_bfloat16* zl = Zl + row * L_;
    #pragma unroll
    for (int i = 0; i < 8; i++) {
        const int j = lane + 32 * i;
        float add = 0.f;
        #pragma unroll
        for (int m = 0; m < M_; m++)
            add = fmaf(attns[w][m], ctxs[m][j], add);
        float v = zs[w][j] + 0.1f * add;
        __nv_bfloat16 h, l;
        split2(v, h, l);
        zh[j] = h; zl[j] = l;
    }
}

// ---------------------------------------------------------------------------
extern "C" void kernel_launch(void* const* d_in, const int* in_sizes, int n_in,
                              void* d_out, int out_size) {
    (void)in_sizes; (void)n_in; (void)out_size;
    const float* x      = (const float*)d_in[0];
    const float* eps    = (const float*)d_in[1];
    const float* enc_w1 = (const float*)d_in[2];
    const float* enc_b1 = (const float*)d_in[3];
    const float* ln1_g  = (const float*)d_in[4];
    const float* ln1_b  = (const float*)d_in[5];
    const float* enc_w2 = (const float*)d_in[6];
    const float* enc_b2 = (const float*)d_in[7];
    const float* ln2_g  = (const float*)d_in[8];
    const float* ln2_b  = (const float*)d_in[9];
    const float* mu_w   = (const float*)d_in[10];
    const float* mu_b   = (const float*)d_in[11];
    const float* lv_w   = (const float*)d_in[12];
    const float* lv_b   = (const float*)d_in[13];
    const float* di_w   = (const float*)d_in[14];
    const float* di_b   = (const float*)d_in[15];
    const float* dec_w1 = (const float*)d_in[16];
    const float* dec_b1 = (const float*)d_in[17];
    const float* dln1_g = (const float*)d_in[18];
    const float* dln1_b = (const float*)d_in[19];
    const float* dec_w2 = (const float*)d_in[20];
    const float* dec_b2 = (const float*)d_in[21];
    const float* dln2_g = (const float*)d_in[22];
    const float* dln2_b = (const float*)d_in[23];
    const float* dec_w3 = (const float*)d_in[24];
    const float* dec_b3 = (const float*)d_in[25];
    const float* ctx    = (const float*)d_in[26];

    float* out     = (float*)d_out;
    float* out_rec = out;
    float* out_mu  = out + (size_t)B_ * D_;
    float* out_lv  = out_mu + (size_t)B_ * L_;

    __nv_bfloat16 *wh, *wl, *p1h, *p1l, *p2h, *p2l;
    float *f32buf, *bias512;
    cudaGetSymbolAddress((void**)&wh, g_wh);
    cudaGetSymbolAddress((void**)&wl, g_wl);
    cudaGetSymbolAddress((void**)&p1h, g_p1h);
    cudaGetSymbolAddress((void**)&p1l, g_p1l);
    cudaGetSymbolAddress((void**)&p2h, g_p2h);
    cudaGetSymbolAddress((void**)&p2l, g_p2l);
    cudaGetSymbolAddress((void**)&f32buf, g_f32);
    cudaGetSymbolAddress((void**)&bias512, g_bias512);

    cudaFuncSetAttribute(mma_gemm_kernel<0>, cudaFuncAttributeMaxDynamicSharedMemorySize, GSMEM);
    cudaFuncSetAttribute(mma_gemm_kernel<1>, cudaFuncAttributeMaxDynamicSharedMemorySize, GSMEM);

    // packed split-weight offsets; mu (o_mu) and lv (o_lv) are contiguous so
    // the mu/lv GEMMs merge into one N=512 pass.
    const size_t o_e1 = 0,       o_e2 = 786432,  o_mu = 1835008, o_lv = 2097152;
    const size_t o_di = 2359296, o_d1 = 2621440, o_d2 = 3670016, o_d3 = 5767168;
    (void)o_lv;

    // packed bias for the merged mu/lv GEMM
    cudaMemcpyAsync(bias512,       mu_b, 256 * sizeof(float), cudaMemcpyDeviceToDevice);
    cudaMemcpyAsync(bias512 + 256, lv_b, 256 * sizeof(float), cudaMemcpyDeviceToDevice);

    const dim3 blk(256);
    auto splt = [&](const float* s, __nv_bfloat16* h, __nv_bfloat16* l, size_t n) {
        int n4 = (int)(n / 4);
        split_kernel<<<(n4 + 255) / 256, blk>>>(s, h, l, n4);
    };

    // splits: input + all weights
    splt(x,      p1h,       p1l,       (size_t)B_ * D_);
    splt(enc_w1, wh + o_e1, wl + o_e1, (size_t)H_ * D_);
    splt(enc_w2, wh + o_e2, wl + o_e2, (size_t)H_ * H_);
    splt(mu_w,   wh + o_mu, wl + o_mu, (size_t)L_ * H_);
    splt(lv_w,   wh + o_lv, wl + o_lv, (size_t)L_ * H_);
    splt(di_w,   wh + o_di, wl + o_di, (size_t)H_ * L_);
    splt(dec_w1, wh + o_d1, wl + o_d1, (size_t)H_ * H_);
    splt(dec_w2, wh + o_d2, wl + o_d2, (size_t)2 * H_ * H_);
    splt(dec_w3, wh + o_d3, wl + o_d3, (size_t)D_ * 2 * H_);

    auto gemm = [&](int mode, const __nv_bfloat16* ah, const __nv_bfloat16* al,
                    size_t wo, const float* bias, float* cf,
                    __nv_bfloat16* oh, __nv_bfloat16* ol, int N, int K) {
        dim3 g(N / 256, B_ / 128);
        if (mode == 0)
            mma_gemm_kernel<0><<<g, blk, GSMEM>>>(ah, al, wh + wo, wl + wo, bias, cf, oh, ol, N, K);
        else
            mma_gemm_kernel<1><<<g, blk, GSMEM>>>(ah, al, wh + wo, wl + wo, bias, cf, oh, ol, N, K);
    };

    // encoder
    gemm(0, p1h, p1l, o_e1, enc_b1, f32buf, nullptr, nullptr, H_, D_);
    ln_split_kernel<1><<<B_, blk>>>(f32buf, ln1_g, ln1_b, p2h, p2l);
    gemm(0, p2h, p2l, o_e2, enc_b2, f32buf, nullptr, nullptr, H_, H_);
    ln_split_kernel<1><<<B_, blk>>>(f32buf, ln2_g, ln2_b, p1h, p1l);
    // merged mu|lv GEMM -> f32buf [B, 512]
    gemm(0, p1h, p1l, o_mu, bias512, f32buf, nullptr, nullptr, 512, H_);
    // reparameterize + context attention (also writes out_mu / out_lv)
    reparam_attn_kernel<<<B_ / 8, blk>>>(f32buf, eps, ctx, out_mu, out_lv, p2h, p2l);
    // decoder
    gemm(1, p2h, p2l, o_di, di_b, nullptr, p1h, p1l, H_, L_);
    gemm(0, p1h, p1l, o_d1, dec_b1, f32buf, nullptr, nullptr, H_, H_);
    ln_split_kernel<1><<<B_, blk>>>(f32buf, dln1_g, dln1_b, p2h, p2l);
    gemm(0, p2h, p2l, o_d2, dec_b2, f32buf, nullptr, nullptr, 2 * H_, H_);
    ln_split_kernel<2><<<B_, blk>>>(f32buf, dln2_g, dln2_b, p1h, p1l);
    gemm(0, p1h, p1l, o_d3, dec_b3, out_rec, nullptr, nullptr, D_, 2 * H_);
}